// round 3
// baseline (speedup 1.0000x reference)
#include <cuda_runtime.h>
#include <math.h>

#define BB     16
#define NVV    128
#define FDD    8192
#define KSPLIT 4
#define KCHUNK (FDD / KSPLIT)   // 2048
#define KT     16
#define EPSF   1e-6f
#define CONSTE (8192.0f * 1e-6f * 1e-6f)  // FD * eps^2
#define TINV   5.0f              // 1 / 0.2
#define MARGINF 1.0f

// ---------------- device scratch (no allocations allowed) ----------------
__device__ float g_Sp[(size_t)KSPLIT * BB * NVV * NVV];  // 4 MB
__device__ float g_Lp[(size_t)KSPLIT * BB * NVV * NVV];  // 4 MB
__device__ float g_S[(size_t)BB * NVV * NVV];            // 1 MB
__device__ float g_L[(size_t)BB * NVV * NVV];            // 1 MB
__device__ float g_inv[3 * BB * NVV];                    // inv norms q,k,n
__device__ float g_sumn[2 * BB * NVV];                   // normalized row sums q,k
__device__ float g_parts[BB * 4];                        // sm, tri, cyc, ce per batch

// ---------------- kernel 1: per-row norms + normalized row sums ----------
__global__ __launch_bounds__(256) void stats_k(const float* __restrict__ q,
                                               const float* __restrict__ k,
                                               const float* __restrict__ n) {
    int blk = blockIdx.x;              // 0 .. 3*BB*NVV-1
    int t = blk / (BB * NVV);
    int r = blk % (BB * NVV);
    const float* src = (t == 0 ? q : (t == 1 ? k : n)) + (size_t)r * FDD;
    float ss = 0.f, su = 0.f;
    for (int c = threadIdx.x * 4; c < FDD; c += 256 * 4) {
        float4 v = *(const float4*)(src + c);
        ss += v.x * v.x + v.y * v.y + v.z * v.z + v.w * v.w;
        su += v.x + v.y + v.z + v.w;
    }
    __shared__ float rs[8], ru[8];
    #pragma unroll
    for (int o = 16; o > 0; o >>= 1) {
        ss += __shfl_xor_sync(0xffffffffu, ss, o);
        su += __shfl_xor_sync(0xffffffffu, su, o);
    }
    int lane = threadIdx.x & 31, w = threadIdx.x >> 5;
    if (lane == 0) { rs[w] = ss; ru[w] = su; }
    __syncthreads();
    if (threadIdx.x == 0) {
        float S = 0.f, U = 0.f;
        #pragma unroll
        for (int i = 0; i < 8; i++) { S += rs[i]; U += ru[i]; }
        float inv = 1.f / fmaxf(sqrtf(S), 1e-12f);
        g_inv[t * BB * NVV + r] = inv;
        if (t < 2) g_sumn[t * BB * NVV + r] = U * inv;
    }
}

// ---------------- kernel 2: raw GEMM partials (q·k^T and q·n^T) ----------
// grid (KSPLIT, 2, BB); 256 threads; 128x128 tile per CTA; 8x8 per thread.
__global__ __launch_bounds__(256) void gemm_k(const float* __restrict__ q,
                                              const float* __restrict__ kk_,
                                              const float* __restrict__ nn_) {
    int b  = blockIdx.z;
    int wh = blockIdx.y;
    int kc = blockIdx.x;
    const float* A  = q + (size_t)b * NVV * FDD;
    const float* Bm = (wh ? nn_ : kk_) + (size_t)b * NVV * FDD;

    __shared__ float As[KT][NVV + 4];
    __shared__ float Bs[KT][NVV + 4];

    float acc[8][8];
    #pragma unroll
    for (int i = 0; i < 8; i++)
        #pragma unroll
        for (int j = 0; j < 8; j++) acc[i][j] = 0.f;

    int tid = threadIdx.x;
    int tx = tid & 15, ty = tid >> 4;
    int k0 = kc * KCHUNK;

    for (int kb = k0; kb < k0 + KCHUNK; kb += KT) {
        float4 va[2], vb[2];
        #pragma unroll
        for (int h = 0; h < 2; h++) {
            int f = tid + h * 256;
            int row = f >> 2;
            int c4 = (f & 3) << 2;
            va[h] = *(const float4*)(A  + (size_t)row * FDD + kb + c4);
            vb[h] = *(const float4*)(Bm + (size_t)row * FDD + kb + c4);
        }
        __syncthreads();
        #pragma unroll
        for (int h = 0; h < 2; h++) {
            int f = tid + h * 256;
            int row = f >> 2;
            int c4 = (f & 3) << 2;
            As[c4 + 0][row] = va[h].x; As[c4 + 1][row] = va[h].y;
            As[c4 + 2][row] = va[h].z; As[c4 + 3][row] = va[h].w;
            Bs[c4 + 0][row] = vb[h].x; Bs[c4 + 1][row] = vb[h].y;
            Bs[c4 + 2][row] = vb[h].z; Bs[c4 + 3][row] = vb[h].w;
        }
        __syncthreads();
        #pragma unroll
        for (int p = 0; p < KT; p++) {
            float a[8], bv[8];
            *(float4*)&a[0]  = *(const float4*)&As[p][ty * 8];
            *(float4*)&a[4]  = *(const float4*)&As[p][ty * 8 + 4];
            *(float4*)&bv[0] = *(const float4*)&Bs[p][tx * 8];
            *(float4*)&bv[4] = *(const float4*)&Bs[p][tx * 8 + 4];
            #pragma unroll
            for (int i = 0; i < 8; i++)
                #pragma unroll
                for (int j = 0; j < 8; j++)
                    acc[i][j] = fmaf(a[i], bv[j], acc[i][j]);
        }
    }

    float* out = (wh ? g_Lp : g_Sp) + ((size_t)kc * BB + b) * (NVV * NVV);
    #pragma unroll
    for (int i = 0; i < 8; i++) {
        #pragma unroll
        for (int j = 0; j < 8; j += 4) {
            *(float4*)&out[(size_t)(ty * 8 + i) * NVV + tx * 8 + j] =
                make_float4(acc[i][j], acc[i][j + 1], acc[i][j + 2], acc[i][j + 3]);
        }
    }
}

// ---------------- kernel 3: sum K-split partials + apply norm scaling ----
__global__ __launch_bounds__(256) void reduce_scale_k() {
    int idx = blockIdx.x * 256 + threadIdx.x;   // over BB*NVV*NVV
    if (idx >= BB * NVV * NVV) return;
    int b = idx >> 14;
    int ij = idx & 16383;
    int i = ij >> 7, j = ij & 127;
    float s = 0.f, l = 0.f;
    #pragma unroll
    for (int p = 0; p < KSPLIT; p++) {
        s += g_Sp[(size_t)p * BB * NVV * NVV + idx];
        l += g_Lp[(size_t)p * BB * NVV * NVV + idx];
    }
    float iq = g_inv[0 * BB * NVV + b * NVV + i];
    g_S[idx] = s * iq * g_inv[1 * BB * NVV + b * NVV + j];
    g_L[idx] = l * iq * g_inv[2 * BB * NVV + b * NVV + j];
}

// ---------------- kernel 4: per-batch loss parts ---------------------------
__global__ __launch_bounds__(256) void epi_k() {
    int b = blockIdx.x;
    const float* S = g_S + (size_t)b * NVV * NVV;
    const float* L = g_L + (size_t)b * NVV * NVV;
    __shared__ float sqv[NVV], skv[NVV], dqk[NVV], dkq[NVV];
    int tid = threadIdx.x;

    if (tid < NVV) {
        sqv[tid] = g_sumn[b * NVV + tid];
        skv[tid] = g_sumn[BB * NVV + b * NVV + tid];
    }
    __syncthreads();
    if (tid < NVV) {
        float Sii = S[tid * NVV + tid];
        dqk[tid] = sqrtf(fmaxf(2.f - 2.f * Sii + 2.f * EPSF * (sqv[tid] - skv[tid]) + CONSTE, 0.f));
        dkq[tid] = sqrtf(fmaxf(2.f - 2.f * Sii + 2.f * EPSF * (skv[tid] - sqv[tid]) + CONSTE, 0.f));
    }
    __syncthreads();

    float smacc = 0.f, triacc = 0.f, cycacc = 0.f, ceacc = 0.f;
    for (int idx = tid; idx < NVV * NVV; idx += 256) {
        int i = idx >> 7, j = idx & 127;
        float Sij = S[idx];
        float d = Sij - (i == j ? 1.f : 0.f);
        smacc += d * d;
        if (i != j) {
            float Sji = S[j * NVV + i];
            cycacc += fabsf(Sij - Sji);
            float dq = sqrtf(fmaxf(2.f - 2.f * Sij + 2.f * EPSF * (sqv[i] - skv[j]) + CONSTE, 0.f));
            triacc += fmaxf(dqk[i] - dq + MARGINF, 0.f);
            float dk = sqrtf(fmaxf(2.f - 2.f * Sji + 2.f * EPSF * (skv[i] - sqv[j]) + CONSTE, 0.f));
            triacc += fmaxf(dkq[i] - dk + MARGINF, 0.f);
        }
    }

    // InfoNCE: one warp per row-group; 129 logits per row (l_pos + 128 negs)
    int lane = tid & 31, w = tid >> 5;
    for (int i = w; i < NVV; i += 8) {
        float lpos = S[i * NVV + i] * TINV;
        float mx = lpos;
        for (int j = lane; j < NVV; j += 32) mx = fmaxf(mx, L[i * NVV + j] * TINV);
        #pragma unroll
        for (int o = 16; o > 0; o >>= 1) mx = fmaxf(mx, __shfl_xor_sync(0xffffffffu, mx, o));
        float se = (lane == 0) ? expf(lpos - mx) : 0.f;
        for (int j = lane; j < NVV; j += 32) se += expf(L[i * NVV + j] * TINV - mx);
        #pragma unroll
        for (int o = 16; o > 0; o >>= 1) se += __shfl_xor_sync(0xffffffffu, se, o);
        if (lane == 0) ceacc += mx + logf(se) - lpos;
    }

    // block reduce the four accumulators
    __shared__ float red[4][8];
    #pragma unroll
    for (int o = 16; o > 0; o >>= 1) {
        smacc  += __shfl_xor_sync(0xffffffffu, smacc,  o);
        triacc += __shfl_xor_sync(0xffffffffu, triacc, o);
        cycacc += __shfl_xor_sync(0xffffffffu, cycacc, o);
        ceacc  += __shfl_xor_sync(0xffffffffu, ceacc,  o);
    }
    if (lane == 0) { red[0][w] = smacc; red[1][w] = triacc; red[2][w] = cycacc; red[3][w] = ceacc; }
    __syncthreads();
    if (tid == 0) {
        float a = 0.f, t = 0.f, c = 0.f, e = 0.f;
        #pragma unroll
        for (int i = 0; i < 8; i++) { a += red[0][i]; t += red[1][i]; c += red[2][i]; e += red[3][i]; }
        g_parts[b * 4 + 0] = a / (float)(NVV * NVV);
        g_parts[b * 4 + 1] = t;
        g_parts[b * 4 + 2] = c / (float)(NVV * (NVV - 1));
        g_parts[b * 4 + 3] = e / (float)(NVV * NVV);   // mean over g, then /g
    }
}

// ---------------- kernel 5: final combine (with the cumsum-over-batches bug)
__global__ void final_k(float* out, int out_size) {
    if (threadIdx.x == 0 && blockIdx.x == 0) {
        float ssl = 0.f, tw = 0.f;
        for (int b = 0; b < BB; b++) {
            ssl += g_parts[b * 4 + 0] + g_parts[b * 4 + 2] + g_parts[b * 4 + 3];
            tw  += (float)(BB - b) * g_parts[b * 4 + 1];   // sum of cumsum
        }
        ssl += tw / (float)(2 * NVV * (NVV - 1));           // tri_cnt = 32512
        for (int i = 0; i < out_size; i++) out[i] = ssl;
    }
}

// ---------------- launch -----------------------------------------------
extern "C" void kernel_launch(void* const* d_in, const int* in_sizes, int n_in,
                              void* d_out, int out_size) {
    const float* q = (const float*)d_in[0];
    const float* k = (const float*)d_in[1];
    const float* n = (const float*)d_in[2];
    // d_in[3] = num_gt; fixed at 128 == NV for this problem's shapes.

    stats_k<<<3 * BB * NVV, 256>>>(q, k, n);
    dim3 gg(KSPLIT, 2, BB);
    gemm_k<<<gg, 256>>>(q, k, n);
    reduce_scale_k<<<(BB * NVV * NVV + 255) / 256, 256>>>();
    epi_k<<<BB, 256>>>();
    final_k<<<1, 32>>>((float*)d_out, out_size);
}

// round 6
// speedup vs baseline: 3.9971x; 3.9971x over previous
#include <cuda_runtime.h>
#include <cuda_bf16.h>
#include <math.h>
#include <stdint.h>

#define BB      16
#define NVV     128
#define FDD     8192
#define ROWS_TOT (BB*NVV)          // 2048 rows per tensor
#define KSPLIT  4
#define KCHUNK  (FDD/KSPLIT)       // 2048
#define NST     4                  // cp.async pipeline stages
#define NITER   (KCHUNK/64)        // 32 k-iterations of 64 bf16
#define TILEB   16384              // one operand tile: 128 rows x 128 B
#define SMEM_TOT (2*NST*TILEB)     // 131072 B

#define EPSF    1e-6f
#define CONSTE  (8192.0f*1e-6f*1e-6f)
#define TINV    5.0f
#define MARGINF 1.0f

// ---------------- device scratch (static; no runtime allocation) --------
__device__ __nv_bfloat16 g_qb[(size_t)ROWS_TOT*FDD];   // 33.5 MB
__device__ __nv_bfloat16 g_kb[(size_t)ROWS_TOT*FDD];
__device__ __nv_bfloat16 g_nb[(size_t)ROWS_TOT*FDD];
__device__ float g_Sp[(size_t)KSPLIT*BB*NVV*NVV];      // 4 MB
__device__ float g_Lp[(size_t)KSPLIT*BB*NVV*NVV];      // 4 MB
__device__ float g_S[(size_t)BB*NVV*NVV];              // 1 MB
__device__ float g_L[(size_t)BB*NVV*NVV];              // 1 MB
__device__ float g_inv[3*ROWS_TOT];
__device__ float g_sumn[2*ROWS_TOT];
__device__ float g_parts2[BB*16*4];                    // per (batch,chunk) raw sums

// ---------------- PTX helpers (all plain-sm_103-safe) --------------------
__device__ __forceinline__ uint32_t s2u(const void* p) {
    uint32_t a;
    asm("{ .reg .u64 t; cvta.to.shared.u64 t, %1; cvt.u32.u64 %0, t; }"
        : "=r"(a) : "l"(p));
    return a;
}
#define CPA16(smem_u32, gptr) \
    asm volatile("cp.async.cg.shared.global [%0], [%1], 16;" \
                 :: "r"(smem_u32), "l"(gptr) : "memory")
#define CPA_COMMIT() asm volatile("cp.async.commit_group;" ::: "memory")
#define CPA_WAIT(n)  asm volatile("cp.async.wait_group %0;" :: "n"(n) : "memory")

// swizzle: 16B chunk c of row r placed at chunk (c ^ (r&7))
__device__ __forceinline__ uint32_t tile_off(int row, int c) {
    return (uint32_t)(row * 128 + ((c ^ (row & 7)) << 4));
}

#define LDMX4(r0, r1, r2, r3, addr) \
    asm volatile("ldmatrix.sync.aligned.m8n8.x4.shared.b16 {%0,%1,%2,%3}, [%4];" \
        : "=r"(r0), "=r"(r1), "=r"(r2), "=r"(r3) : "r"(addr))

#define MMA16816(d, a, b0, b1) \
    asm volatile("mma.sync.aligned.m16n8k16.row.col.f32.bf16.bf16.f32 " \
        "{%0,%1,%2,%3}, {%4,%5,%6,%7}, {%8,%9}, {%0,%1,%2,%3};" \
        : "+f"((d)[0]), "+f"((d)[1]), "+f"((d)[2]), "+f"((d)[3]) \
        : "r"((a)[0]), "r"((a)[1]), "r"((a)[2]), "r"((a)[3]), "r"(b0), "r"(b1))

// ---------------- kernel 1: fused stats + bf16 conversion ----------------
__global__ __launch_bounds__(256) void prep_k(const float* __restrict__ q,
                                              const float* __restrict__ k,
                                              const float* __restrict__ n) {
    int blk = blockIdx.x;                  // 0 .. 3*ROWS_TOT-1
    int t = blk / ROWS_TOT;
    int r = blk % ROWS_TOT;
    const float* src = (t == 0 ? q : (t == 1 ? k : n)) + (size_t)r * FDD;
    __nv_bfloat16* dst = (t == 0 ? g_qb : (t == 1 ? g_kb : g_nb)) + (size_t)r * FDD;

    float ss = 0.f, su = 0.f;
    for (int c = threadIdx.x * 8; c < FDD; c += 256 * 8) {
        float4 v0 = *(const float4*)(src + c);
        float4 v1 = *(const float4*)(src + c + 4);
        ss += v0.x*v0.x + v0.y*v0.y + v0.z*v0.z + v0.w*v0.w
            + v1.x*v1.x + v1.y*v1.y + v1.z*v1.z + v1.w*v1.w;
        su += v0.x + v0.y + v0.z + v0.w + v1.x + v1.y + v1.z + v1.w;
        union { __nv_bfloat162 h[4]; uint4 u; } pk;
        pk.h[0] = __float22bfloat162_rn(make_float2(v0.x, v0.y));
        pk.h[1] = __float22bfloat162_rn(make_float2(v0.z, v0.w));
        pk.h[2] = __float22bfloat162_rn(make_float2(v1.x, v1.y));
        pk.h[3] = __float22bfloat162_rn(make_float2(v1.z, v1.w));
        *(uint4*)(dst + c) = pk.u;
    }
    __shared__ float rs[8], ru[8];
    #pragma unroll
    for (int o = 16; o > 0; o >>= 1) {
        ss += __shfl_xor_sync(0xffffffffu, ss, o);
        su += __shfl_xor_sync(0xffffffffu, su, o);
    }
    int lane = threadIdx.x & 31, w = threadIdx.x >> 5;
    if (lane == 0) { rs[w] = ss; ru[w] = su; }
    __syncthreads();
    if (threadIdx.x == 0) {
        float S = 0.f, U = 0.f;
        #pragma unroll
        for (int i = 0; i < 8; i++) { S += rs[i]; U += ru[i]; }
        float inv = 1.f / fmaxf(sqrtf(S), 1e-12f);
        g_inv[t * ROWS_TOT + r] = inv;
        if (t < 2) g_sumn[t * ROWS_TOT + r] = U * inv;
    }
}

// ---------------- kernel 2: mma.sync bf16 GEMM partials ------------------
// grid (KSPLIT, 2, BB), 256 threads. CTA computes a 128x128 x KCHUNK chunk.
// 8 warps as 2x4: warptile 64(M) x 32(N) = 4x4 m16n8k16 fragments.
__device__ __forceinline__ void load_tile(uint32_t smA, uint32_t smB,
                                          const __nv_bfloat16* A,
                                          const __nv_bfloat16* Bm,
                                          int kelem, int tid) {
    #pragma unroll
    for (int h = 0; h < 4; h++) {
        int l = tid + h * 256;            // 0..1023 chunks of 16B
        int row = l >> 3;
        int c = l & 7;
        uint32_t off = tile_off(row, c);
        const char* ga = (const char*)(A  + (size_t)row * FDD + kelem) + c * 16;
        const char* gb = (const char*)(Bm + (size_t)row * FDD + kelem) + c * 16;
        CPA16(smA + off, ga);
        CPA16(smB + off, gb);
    }
}

__global__ __launch_bounds__(256) void mma_k() {
    extern __shared__ char smem[];
    int tid = threadIdx.x, wid = tid >> 5, lane = tid & 31;
    int wm = wid & 1, wn = wid >> 1;      // 2 x 4 warp grid
    int kc = blockIdx.x, wh = blockIdx.y, b = blockIdx.z;
    const __nv_bfloat16* A  = g_qb + (size_t)(b * NVV) * FDD;
    const __nv_bfloat16* Bm = (wh ? g_nb : g_kb) + (size_t)(b * NVV) * FDD;
    int k0 = kc * KCHUNK;

    uint32_t sbase = s2u(smem);
    uint32_t tilesA = sbase;
    uint32_t tilesB = sbase + NST * TILEB;

    float acc[4][4][4];
    #pragma unroll
    for (int mi = 0; mi < 4; mi++)
        #pragma unroll
        for (int ni = 0; ni < 4; ni++)
            #pragma unroll
            for (int e = 0; e < 4; e++) acc[mi][ni][e] = 0.f;

    // precompute ldmatrix base rows/cols for this lane
    int a_row = wm * 64 + (lane & 15);          // + mi*16
    int a_chi = (lane >> 4);                    // + kk*2
    int b_row = wn * 32 + (lane & 7) + ((lane & 16) ? 8 : 0);  // + nh*16
    int b_chi = (lane >> 3) & 1;                // + kk*2

    // prologue: fill NST-1 stages
    #pragma unroll
    for (int s = 0; s < NST - 1; s++) {
        load_tile(tilesA + s * TILEB, tilesB + s * TILEB, A, Bm, k0 + s * 64, tid);
        CPA_COMMIT();
    }

    for (int it = 0; it < NITER; it++) {
        int nxt = it + NST - 1;
        if (nxt < NITER) {
            int sn = nxt % NST;
            load_tile(tilesA + sn * TILEB, tilesB + sn * TILEB, A, Bm, k0 + nxt * 64, tid);
        }
        CPA_COMMIT();
        CPA_WAIT(NST - 1);                 // stage 'it' complete
        __syncthreads();

        uint32_t smA = tilesA + (it % NST) * TILEB;
        uint32_t smB = tilesB + (it % NST) * TILEB;
        #pragma unroll
        for (int kk = 0; kk < 4; kk++) {
            uint32_t af[4][4];
            #pragma unroll
            for (int mi = 0; mi < 4; mi++) {
                int row = a_row + mi * 16;
                LDMX4(af[mi][0], af[mi][1], af[mi][2], af[mi][3],
                      smA + tile_off(row, kk * 2 + a_chi));
            }
            uint32_t bf[2][4];
            #pragma unroll
            for (int nh = 0; nh < 2; nh++) {
                int row = b_row + nh * 16;
                LDMX4(bf[nh][0], bf[nh][1], bf[nh][2], bf[nh][3],
                      smB + tile_off(row, kk * 2 + b_chi));
            }
            #pragma unroll
            for (int mi = 0; mi < 4; mi++)
                #pragma unroll
                for (int ni = 0; ni < 4; ni++)
                    MMA16816(acc[mi][ni], af[mi],
                             bf[ni >> 1][(ni & 1) * 2], bf[ni >> 1][(ni & 1) * 2 + 1]);
        }
        __syncthreads();                   // slot reused by next iteration's load
    }

    // epilogue: write fp32 partials
    float* out = (wh ? g_Lp : g_Sp) + ((size_t)kc * BB + b) * (NVV * NVV);
    int gr = lane >> 2, tc = lane & 3;
    #pragma unroll
    for (int mi = 0; mi < 4; mi++) {
        #pragma unroll
        for (int ni = 0; ni < 4; ni++) {
            int r0 = wm * 64 + mi * 16 + gr;
            int col = wn * 32 + ni * 8 + tc * 2;
            *(float2*)&out[(size_t)r0 * NVV + col] =
                make_float2(acc[mi][ni][0], acc[mi][ni][1]);
            *(float2*)&out[(size_t)(r0 + 8) * NVV + col] =
                make_float2(acc[mi][ni][2], acc[mi][ni][3]);
        }
    }
}

// ---------------- kernel 3: sum K-split partials + apply norm scaling ----
__global__ __launch_bounds__(256) void reduce_scale_k() {
    int idx = blockIdx.x * 256 + threadIdx.x;
    if (idx >= BB * NVV * NVV) return;
    int b = idx >> 14;
    int ij = idx & 16383;
    int i = ij >> 7, j = ij & 127;
    float s = 0.f, l = 0.f;
    #pragma unroll
    for (int p = 0; p < KSPLIT; p++) {
        s += g_Sp[(size_t)p * BB * NVV * NVV + idx];
        l += g_Lp[(size_t)p * BB * NVV * NVV + idx];
    }
    float iq = g_inv[0 * ROWS_TOT + b * NVV + i];
    g_S[idx] = s * iq * g_inv[1 * ROWS_TOT + b * NVV + j];
    g_L[idx] = l * iq * g_inv[2 * ROWS_TOT + b * NVV + j];
}

// ---------------- kernel 4: parallel epilogue -----------------------------
// grid (16, BB): 8 rows of the 128x128 matrices per CTA.
__global__ __launch_bounds__(256) void epi2_k() {
    int chunk = blockIdx.x, b = blockIdx.y;
    const float* S = g_S + (size_t)b * NVV * NVV;
    const float* L = g_L + (size_t)b * NVV * NVV;
    __shared__ float sqv[NVV], skv[NVV], dqk_d[NVV], dkq_d[NVV];
    int tid = threadIdx.x;

    if (tid < NVV) {
        float sq = g_sumn[b * NVV + tid];
        float sk = g_sumn[ROWS_TOT + b * NVV + tid];
        sqv[tid] = sq; skv[tid] = sk;
        float Sii = S[tid * NVV + tid];
        dqk_d[tid] = sqrtf(fmaxf(2.f - 2.f * Sii + 2.f * EPSF * (sq - sk) + CONSTE, 0.f));
        dkq_d[tid] = sqrtf(fmaxf(2.f - 2.f * Sii + 2.f * EPSF * (sk - sq) + CONSTE, 0.f));
    }
    __syncthreads();

    float smacc = 0.f, triacc = 0.f, cycacc = 0.f, ceacc = 0.f;
    #pragma unroll
    for (int h = 0; h < 4; h++) {
        int idx = h * 256 + tid;           // 0..1023 over 8 rows x 128 cols
        int il = idx >> 7, j = idx & 127;
        int i = chunk * 8 + il;
        float Sij = S[i * NVV + j];
        if (i == j) {
            float d = Sij - 1.f; smacc += d * d;
        } else {
            smacc += Sij * Sij;
            float Sji = S[j * NVV + i];
            cycacc += fabsf(Sij - Sji);
            // tri1: anc=q_i, pos=k_i, neg=k_j
            float dq = sqrtf(fmaxf(2.f - 2.f * Sij + 2.f * EPSF * (sqv[i] - skv[j]) + CONSTE, 0.f));
            triacc += fmaxf(dqk_d[i] - dq + MARGINF, 0.f);
            // tri2 reindexed over (i,j): relu(dkq[j] - d(S_ij; sk[j], sq[i]) + M)
            float dk = sqrtf(fmaxf(2.f - 2.f * Sij + 2.f * EPSF * (skv[j] - sqv[i]) + CONSTE, 0.f));
            triacc += fmaxf(dkq_d[j] - dk + MARGINF, 0.f);
        }
    }

    // InfoNCE: warp w handles row chunk*8 + w (129 logits)
    int lane = tid & 31, w = tid >> 5;
    {
        int i = chunk * 8 + w;
        float lpos = S[i * NVV + i] * TINV;
        float mx = lpos;
        for (int j = lane; j < NVV; j += 32) mx = fmaxf(mx, L[i * NVV + j] * TINV);
        #pragma unroll
        for (int o = 16; o > 0; o >>= 1) mx = fmaxf(mx, __shfl_xor_sync(0xffffffffu, mx, o));
        float se = (lane == 0) ? expf(lpos - mx) : 0.f;
        for (int j = lane; j < NVV; j += 32) se += expf(L[i * NVV + j] * TINV - mx);
        #pragma unroll
        for (int o = 16; o > 0; o >>= 1) se += __shfl_xor_sync(0xffffffffu, se, o);
        if (lane == 0) ceacc = mx + logf(se) - lpos;
    }

    __shared__ float red[4][8];
    #pragma unroll
    for (int o = 16; o > 0; o >>= 1) {
        smacc  += __shfl_xor_sync(0xffffffffu, smacc,  o);
        triacc += __shfl_xor_sync(0xffffffffu, triacc, o);
        cycacc += __shfl_xor_sync(0xffffffffu, cycacc, o);
        ceacc  += __shfl_xor_sync(0xffffffffu, ceacc,  o);
    }
    if (lane == 0) { red[0][w] = smacc; red[1][w] = triacc; red[2][w] = cycacc; red[3][w] = ceacc; }
    __syncthreads();
    if (tid == 0) {
        float a = 0.f, t = 0.f, c = 0.f, e = 0.f;
        #pragma unroll
        for (int i = 0; i < 8; i++) { a += red[0][i]; t += red[1][i]; c += red[2][i]; e += red[3][i]; }
        float* p = &g_parts2[(b * 16 + chunk) * 4];
        p[0] = a; p[1] = t; p[2] = c; p[3] = e;
    }
}

// ---------------- kernel 5: final combine (keeps the cumsum-batches bug) --
__global__ void final_k(float* out, int out_size) {
    if (threadIdx.x == 0 && blockIdx.x == 0) {
        float ssl = 0.f, tw = 0.f;
        for (int b = 0; b < BB; b++) {
            float sm = 0.f, tri = 0.f, cyc = 0.f, ce = 0.f;
            for (int c2 = 0; c2 < 16; c2++) {
                const float* p = &g_parts2[(b * 16 + c2) * 4];
                sm += p[0]; tri += p[1]; cyc += p[2]; ce += p[3];
            }
            ssl += sm / (float)(NVV * NVV) + cyc / (float)(NVV * (NVV - 1))
                 + ce / (float)(NVV * NVV);
            tw += (float)(BB - b) * tri;       // sum of cumsum
        }
        ssl += tw / (float)(2 * NVV * (NVV - 1));
        for (int i = 0; i < out_size; i++) out[i] = ssl;
    }
}

// ---------------- launch -----------------------------------------------
extern "C" void kernel_launch(void* const* d_in, const int* in_sizes, int n_in,
                              void* d_out, int out_size) {
    const float* q = (const float*)d_in[0];
    const float* k = (const float*)d_in[1];
    const float* n = (const float*)d_in[2];
    // d_in[3] = num_gt; fixed at 128 == NV for these shapes.

    static int smem_set = 0;
    if (!smem_set) {
        cudaFuncSetAttribute(mma_k, cudaFuncAttributeMaxDynamicSharedMemorySize, SMEM_TOT);
        smem_set = 1;
    }

    prep_k<<<3 * ROWS_TOT, 256>>>(q, k, n);
    dim3 gg(KSPLIT, 2, BB);
    mma_k<<<gg, 256, SMEM_TOT>>>();
    reduce_scale_k<<<(BB * NVV * NVV + 255) / 256, 256>>>();
    dim3 ge(16, BB);
    epi2_k<<<ge, 256>>>();
    final_k<<<1, 32>>>((float*)d_out, out_size);
}